// round 5
// baseline (speedup 1.0000x reference)
#include <cuda_runtime.h>
#include <cstdint>
#include <math.h>

#define NN      100000
#define EE      1600000
#define DD      32
#define NUMC    1024
#define NBINS   65536
#define CAP     4096
#define SORTN   4096

// ---------------- scratch (static __device__, zero-init; kernels self-clean) ----
__device__ int   g_cnt[NN];
__device__ int   g_rowptr[NN + 1];
__device__ int   g_cursor[NN];
__device__ int   g_bsums[128];
__device__ unsigned int g_csr[EE];
__device__ int   g_c1[NN], g_c2[NN], g_c3[NN];
__device__ float g_embA[NN * DD], g_embB[NN * DD], g_esum[NN * DD];
__device__ float g_numA[NN], g_numB[NN], g_nsum[NN];
__device__ float g_scores[NN];
__device__ int   g_hist[NBINS];
__device__ int   g_pivotB;
__device__ unsigned long long g_cand[CAP];
__device__ int   g_candcnt;

// ---------------- threefry2x32 (exact JAX) ----------------
static __host__ __device__ inline void tf2x32(uint32_t k0, uint32_t k1,
                                              uint32_t x0, uint32_t x1,
                                              uint32_t& o0, uint32_t& o1) {
    uint32_t ks2 = k0 ^ k1 ^ 0x1BD11BDAu;
    x0 += k0; x1 += k1;
#define TF_R(r) { x0 += x1; x1 = (x1 << r) | (x1 >> (32 - r)); x1 ^= x0; }
    TF_R(13) TF_R(15) TF_R(26) TF_R(6)   x0 += k1;  x1 += ks2 + 1u;
    TF_R(17) TF_R(29) TF_R(16) TF_R(24)  x0 += ks2; x1 += k0 + 2u;
    TF_R(13) TF_R(15) TF_R(26) TF_R(6)   x0 += k0;  x1 += k1 + 3u;
    TF_R(17) TF_R(29) TF_R(16) TF_R(24)  x0 += k1;  x1 += ks2 + 4u;
    TF_R(13) TF_R(15) TF_R(26) TF_R(6)   x0 += ks2; x1 += k0 + 5u;
#undef TF_R
    o0 = x0; o1 = x1;
}

// partitionable-mode bits for element j: xor of outputs, counter (0, j)
static __device__ inline uint32_t tf_bits(uint32_t k0, uint32_t k1, uint32_t j) {
    uint32_t o0, o1;
    tf2x32(k0, k1, 0u, j, o0, o1);
    return o0 ^ o1;
}

__device__ inline float u01(uint32_t b) {
    return __uint_as_float((b >> 9) | 0x3f800000u) - 1.0f;
}

__device__ inline float wsum(float v) {
    #pragma unroll
    for (int o = 16; o; o >>= 1) v += __shfl_xor_sync(0xffffffffu, v, o);
    return v;
}
__device__ inline int wsumi(int v) {
    #pragma unroll
    for (int o = 16; o; o >>= 1) v += __shfl_xor_sync(0xffffffffu, v, o);
    return v;
}

// ---------------- kernels ----------------
__global__ void k_hist_rows(const int4* __restrict__ rows4) {
    int i = blockIdx.x * blockDim.x + threadIdx.x;
    if (i >= EE / 4) return;
    int4 r = rows4[i];
    atomicAdd(&g_cnt[r.x], 1);
    atomicAdd(&g_cnt[r.y], 1);
    atomicAdd(&g_cnt[r.z], 1);
    atomicAdd(&g_cnt[r.w], 1);
}

__global__ void k_scanA() {
    __shared__ int s[1024];
    int t = threadIdx.x;
    int i = blockIdx.x * 1024 + t;
    int v = (i < NN) ? g_cnt[i] : 0;
    if (i < NN) g_cnt[i] = 0;           // self-clean for next run
    s[t] = v;
    __syncthreads();
    for (int off = 1; off < 1024; off <<= 1) {
        int x = (t >= off) ? s[t - off] : 0;
        __syncthreads();
        s[t] += x;
        __syncthreads();
    }
    if (i < NN) g_rowptr[i + 1] = s[t];
    if (t == 1023) g_bsums[blockIdx.x] = s[1023];
}

// block-prefix offset computed inline (replaces serial scanB)
__global__ void k_scanC() {
    __shared__ int offs;
    int t = threadIdx.x;
    if (t < 32) {
        int s = 0;
        for (int i = t; i < (int)blockIdx.x; i += 32) s += g_bsums[i];
        s = wsumi(s);
        if (t == 0) offs = s;
    }
    __syncthreads();
    int i = blockIdx.x * 1024 + t;
    if (i < NN) {
        int v = g_rowptr[i + 1] + offs;
        g_rowptr[i + 1] = v;
        if (i + 1 < NN) g_cursor[i + 1] = v;
    }
    if (i == 0) { g_rowptr[0] = 0; g_cursor[0] = 0; }
}

// scatter edges into CSR with inline compounding dropout (integer-exact)
// sortkey = ((7-m)<<24) | col  -> ascending sort = mask-desc, col-asc
__global__ void k_scatter(const int* __restrict__ rows, const int* __restrict__ cols,
                          uint32_t a0, uint32_t a1, uint32_t b0, uint32_t b1,
                          uint32_t c0, uint32_t c1) {
    int e = blockIdx.x * blockDim.x + threadIdx.x;
    if (e >= EE) return;

    // keep iff floor(u01(bits)+p) != 0  <=>  bits >= (1-p) thresholds (exact)
    unsigned int m = 0;
    if (tf_bits(a0, a1, (uint32_t)e) >= 0x80000000u) {
        m = 1u;
        if (tf_bits(b0, b1, (uint32_t)e) >= 0xC0000000u) {
            m = 3u;
            if (tf_bits(c0, c1, (uint32_t)e) >= 0xE0000000u) m = 7u;
        }
    }

    int r = rows[e];
    unsigned int sk = ((7u - m) << 24) | (unsigned int)cols[e];
    int p = atomicAdd(&g_cursor[r], 1);
    g_csr[p] = sk;
}

// fused: warp-per-row register bitonic sort + prefix counts + stage-0 gather
__global__ void k_sortstage0(const float* __restrict__ emb) {
    const unsigned full = 0xffffffffu;
    int gw = (blockIdx.x * blockDim.x + threadIdx.x) >> 5;
    int lane = threadIdx.x & 31;
    if (gw >= NN) return;
    int b = g_rowptr[gw], e = g_rowptr[gw + 1];
    int d = e - b;
    const uint32_t PAD = 0xFFFFFFFFu;
    int c1 = 0, c2 = 0, c3 = 0;
    float acc = 0.f;

    if (d <= 32) {
        uint32_t a = (lane < d) ? g_csr[b + lane] : PAD;
        c1 = __popc(__ballot_sync(full, a < 0x07000000u));
        c2 = __popc(__ballot_sync(full, a < 0x05000000u));
        c3 = __popc(__ballot_sync(full, a < 0x01000000u));
        #pragma unroll
        for (int k = 2; k <= 32; k <<= 1) {
            #pragma unroll
            for (int j = k >> 1; j > 0; j >>= 1) {
                uint32_t y = __shfl_xor_sync(full, a, j);
                bool asc = ((lane & k) == 0);
                bool low = ((lane & j) == 0);
                uint32_t mn = min(a, y), mx = max(a, y);
                a = (low == asc) ? mn : mx;
            }
        }
        if (lane < c1) g_csr[b + lane] = a;  // only kept prefix is re-read later
        for (int i = 0; i < d; i++) {
            uint32_t key = __shfl_sync(full, a, i);
            acc += emb[(key & 0x00FFFFFFu) * DD + lane];
        }
    } else if (d <= 64) {
        uint32_t x0 = (lane < d) ? g_csr[b + lane] : PAD;
        uint32_t x1 = (lane + 32 < d) ? g_csr[b + lane + 32] : PAD;
        c1 = __popc(__ballot_sync(full, x0 < 0x07000000u)) +
             __popc(__ballot_sync(full, x1 < 0x07000000u));
        c2 = __popc(__ballot_sync(full, x0 < 0x05000000u)) +
             __popc(__ballot_sync(full, x1 < 0x05000000u));
        c3 = __popc(__ballot_sync(full, x0 < 0x01000000u)) +
             __popc(__ballot_sync(full, x1 < 0x01000000u));
        #pragma unroll
        for (int k = 2; k <= 64; k <<= 1) {
            #pragma unroll
            for (int j = k >> 1; j > 0; j >>= 1) {
                if (j == 32) {
                    uint32_t mn = min(x0, x1), mx = max(x0, x1);
                    x0 = mn; x1 = mx;
                } else {
                    bool asc0 = ((lane & k) == 0);
                    bool asc1 = (((lane + 32) & k) == 0);
                    bool low = ((lane & j) == 0);
                    uint32_t y0 = __shfl_xor_sync(full, x0, j);
                    uint32_t y1 = __shfl_xor_sync(full, x1, j);
                    uint32_t mn0 = min(x0, y0), mx0 = max(x0, y0);
                    uint32_t mn1 = min(x1, y1), mx1 = max(x1, y1);
                    x0 = (low == asc0) ? mn0 : mx0;
                    x1 = (low == asc1) ? mn1 : mx1;
                }
            }
        }
        if (lane < c1) g_csr[b + lane] = x0;
        if (lane + 32 < c1) g_csr[b + lane + 32] = x1;
        int dlo = (d < 32) ? d : 32;
        for (int i = 0; i < dlo; i++) {
            uint32_t key = __shfl_sync(full, x0, i);
            acc += emb[(key & 0x00FFFFFFu) * DD + lane];
        }
        for (int i = 0; i < d - 32; i++) {
            uint32_t key = __shfl_sync(full, x1, i);
            acc += emb[(key & 0x00FFFFFFu) * DD + lane];
        }
    } else {
        if (lane == 0) {
            for (int i = b + 1; i < e; i++) {
                unsigned int v = g_csr[i]; int j = i - 1;
                while (j >= b && g_csr[j] > v) { g_csr[j + 1] = g_csr[j]; j--; }
                g_csr[j + 1] = v;
            }
            for (int i = b; i < e; i++) {
                uint32_t t = g_csr[i] >> 24;
                c1 += (t < 7); c2 += (t < 5); c3 += (t < 1);
            }
        }
        __syncwarp(full);
        c1 = __shfl_sync(full, c1, 0);
        c2 = __shfl_sync(full, c2, 0);
        c3 = __shfl_sync(full, c3, 0);
        for (int i = b; i < e; i++)
            acc += emb[(g_csr[i] & 0x00FFFFFFu) * DD + lane];
    }

    float self = emb[gw * DD + lane];
    float o = acc - self;
    g_embA[gw * DD + lane] = o;
    g_esum[gw * DD + lane] = o;
    if (lane == 0) {
        g_c1[gw] = c1; g_c2[gw] = c2; g_c3[gw] = c3;
        g_numA[gw] = (float)d;
        g_nsum[gw] = (float)d;
    }
}

template <int S>
__global__ void k_stage() {
    const float* ep;  float* enx;
    const float* np;  float* nn;
    const int* cb;    const int* cprev;
    if (S == 1)      { ep = g_embA; enx = g_embB; np = g_numA; nn = g_numB; cb = g_c1; cprev = nullptr; }
    else if (S == 2) { ep = g_embB; enx = g_embA; np = g_numB; nn = g_numA; cb = g_c2; cprev = g_c1; }
    else             { ep = g_embA; enx = g_embB; np = g_numA; nn = g_numB; cb = g_c3; cprev = g_c2; }

    int gw = (blockIdx.x * blockDim.x + threadIdx.x) >> 5;
    int lane = threadIdx.x & 31;
    if (gw >= NN) return;
    int b = g_rowptr[gw];
    int cnt = cb[gw];
    float ov = (S == 1) ? (float)(g_rowptr[gw + 1] - b) : (float)cprev[gw];

    float acc = 0.f;
    for (int i = b; i < b + cnt; i++)
        acc += ep[(g_csr[i] & 0x00FFFFFFu) * DD + lane];

    float na = 0.f;
    for (int i = b + lane; i < b + cnt; i += 32)
        na += np[g_csr[i] & 0x00FFFFFFu];
    na = wsum(na);

    float self = ep[gw * DD + lane];
    float o = acc - self - ov * self;
    enx[gw * DD + lane] = o;
    g_esum[gw * DD + lane] += o;
    if (lane == 0) {
        float nv = na - np[gw] - ov;
        nn[gw] = nv;
        g_nsum[gw] += nv;
    }
}

__global__ void k_score(const float* __restrict__ emb, float* outS) {
    int gw = (blockIdx.x * blockDim.x + threadIdx.x) >> 5;
    int lane = threadIdx.x & 31;
    if (gw >= NN) return;
    float ns = g_nsum[gw] + 1e-8f;
    float sd = g_esum[gw * DD + lane] / ns;
    float ed = emb[gw * DD + lane];
    float ss = wsum(sd * sd);
    float ee = wsum(ed * ed);
    float sn  = fmaxf(sqrtf(ss), 1e-12f);
    float en2 = fmaxf(sqrtf(ee), 1e-12f);
    float dot = wsum((sd / sn) * (ed / en2));
    if (lane == 0) {
        float gum = -logf(-logf(u01(tf_bits(0u, 7u, (uint32_t)gw))));
        float sc = dot + gum;
        g_scores[gw] = sc;
        if (outS) outS[gw] = sc;
        unsigned bits = __float_as_uint(sc);
        unsigned key = bits ^ ((bits & 0x80000000u) ? 0xFFFFFFFFu : 0x80000000u);
        atomicAdd(&g_hist[key >> 16], 1);
    }
}

__global__ void k_pivot() {
    __shared__ int ssum[1024];
    int t = threadIdx.x;
    int s = 0;
    int loc[64];
    #pragma unroll
    for (int i = 0; i < 64; i++) { loc[i] = g_hist[t * 64 + i]; s += loc[i]; }
    #pragma unroll
    for (int i = 0; i < 64; i++) g_hist[t * 64 + i] = 0;   // self-clean
    ssum[t] = s;
    __syncthreads();
    if (t == 0) {
        int run = 0, B = 0;
        for (int st = 1023; st >= 0; st--) {
            if (run + ssum[st] >= NUMC) {
                // re-walk fine bins of this superbin using shared-cleaned data:
                // we zeroed g_hist, so recompute from ssum is impossible; instead
                // thread 0 rescans its own cached copy only if st==0's... use gather:
                B = st;  // coarse superbin; refine below via second pass variable
                break;
            }
            run += ssum[st];
        }
        // store coarse info: pivot = first fine bin of superbin B; count above
        // superbin B is run (< NUMC). Taking the whole superbin keeps >= NUMC
        // candidates; CAP=4096 absorbs the worst case (superbin of ~3000 only
        // if extreme ties). pivotB = B*64 guarantees >= 1024 candidates.
        g_pivotB = B * 64;
    }
}

__global__ void k_compact() {
    int n = blockIdx.x * blockDim.x + threadIdx.x;
    if (n >= NN) return;
    unsigned bits = __float_as_uint(g_scores[n]);
    unsigned key = bits ^ ((bits & 0x80000000u) ? 0xFFFFFFFFu : 0x80000000u);
    if ((int)(key >> 16) >= g_pivotB) {
        int p = atomicAdd(&g_candcnt, 1);
        if (p < CAP)
            g_cand[p] = ((unsigned long long)key << 32) |
                        (unsigned long long)(0xFFFFFFFFu - (unsigned)n);
    }
}

__global__ void k_sorttop(float* outC) {
    __shared__ unsigned long long s[SORTN];
    int t = threadIdx.x;
    int cnt = g_candcnt; if (cnt > CAP) cnt = CAP;
    for (int i = t; i < SORTN; i += 1024)
        s[i] = (i < cnt) ? g_cand[i] : 0ULL;
    __syncthreads();
    if (t == 0) g_candcnt = 0;   // self-clean
    for (int k = 2; k <= SORTN; k <<= 1) {
        for (int j = k >> 1; j > 0; j >>= 1) {
            for (int i = t; i < SORTN; i += 1024) {
                int ixj = i ^ j;
                if (ixj > i) {
                    unsigned long long a = s[i], b = s[ixj];
                    bool desc = (i & k) == 0;   // final order: descending
                    bool sw = desc ? (a < b) : (a > b);
                    if (sw) { s[i] = b; s[ixj] = a; }
                }
            }
            __syncthreads();
        }
    }
    if (t < NUMC && outC)
        outC[t] = (float)(0xFFFFFFFFu - (unsigned)(s[t] & 0xFFFFFFFFull));
}

// ---------------- launch ----------------
extern "C" void kernel_launch(void* const* d_in, const int* in_sizes, int n_in,
                              void* d_out, int out_size) {
    const int* ei = (const int*)d_in[0];       // edge_index [2, E]
    const int* rows = ei;
    const int* cols = ei + EE;
    const float* emb = (const float*)d_in[2];  // embeds [N, 32]
    float* out = (float*)d_out;

    float* outS = nullptr; float* outC = nullptr;
    if (out_size >= NN + NUMC)      { outS = out; outC = out + NN; }
    else if (out_size == NUMC)      { outC = out; }
    else                            { outS = out; }

    // fold_in(key(42), i) = threefry_2x32((0,42), [0, i]) -> new key (o0, o1)
    uint32_t dk0[3], dk1[3];
    for (uint32_t i = 0; i < 3; i++) tf2x32(0u, 42u, 0u, i, dk0[i], dk1[i]);

    const int T = 256;
    k_hist_rows<<<(EE / 4 + T - 1) / T, T>>>((const int4*)rows);
    k_scanA<<<(NN + 1023) / 1024, 1024>>>();
    k_scanC<<<(NN + 1023) / 1024, 1024>>>();
    k_scatter<<<(EE + T - 1) / T, T>>>(rows, cols,
                                       dk0[0], dk1[0], dk0[1], dk1[1], dk0[2], dk1[2]);
    const int WB = 12500; // 100000 warps / 8 warps per 256-thread block
    k_sortstage0<<<WB, 256>>>(emb);
    k_stage<1><<<WB, 256>>>();
    k_stage<2><<<WB, 256>>>();
    k_stage<3><<<WB, 256>>>();
    k_score<<<WB, 256>>>(emb, outS);
    k_pivot<<<1, 1024>>>();
    k_compact<<<(NN + T - 1) / T, T>>>();
    k_sorttop<<<1, 1024>>>(outC);
}